// round 5
// baseline (speedup 1.0000x reference)
#include <cuda_runtime.h>
#include <math.h>

// ---------------- Problem constants ----------------
#define NQ    8
#define DDIM  1024
#define CD    32
#define KC    1024
#define BB    16
#define TT    4096
#define TILE  32
#define NTHR  256
#define NBLK  ((BB*TT)/TILE)                 // 2048 CTAs
#define QOFF  ((size_t)BB*DDIM*TT)
#define IOFF  (QOFF + (size_t)NQ*BB*TT)

// Shared memory layout (floats)
#define SM_R    0
#define SM_W    (DDIM*33)
#define SM_ZE   (SM_W + CD*256)
#define SM_ENC  (SM_ZE + CD*33)
#define SM_ZQ   (SM_ENC + CD*33)
#define SM_BV   (SM_ZQ + CD*33)
#define SM_BI   (SM_BV + 256)
#define SM_FLOATS (SM_BI + 256)
#define SMEM_BYTES (SM_FLOATS * 4)

__device__ float g_cbn_v5[NQ*KC*CD];
__device__ float g_losspart_v5[NQ*NBLK];

// ---------------- Kernel 0: normalize codebook rows ----------------
// jnp mimicry: squares rounded individually, summed strictly ascending with
// plain adds; n = max(sqrt(ss), 1e-12); cbn = v / n with IEEE division.
__global__ void rvq_normalize_v5(const float* __restrict__ cb) {
    int i = blockIdx.x * blockDim.x + threadIdx.x;   // (q*KC + k)
    if (i >= NQ*KC) return;
    const float* src = cb + (size_t)i * CD;
    float v[CD];
    float ss = 0.f;
#pragma unroll
    for (int c = 0; c < CD; c++) {
        v[c] = src[c];
        float vv = v[c] * v[c];
        ss = ss + vv;
    }
    float n = fmaxf(sqrtf(ss), 1e-12f);
    float* dst = g_cbn_v5 + (size_t)i * CD;
#pragma unroll
    for (int c = 0; c < CD; c++) dst[c] = v[c] / n;
}

// ---------------- Kernel 1: fused residual VQ ----------------
__global__ __launch_bounds__(NTHR, 1)
void rvq_main_v5(const float* __restrict__ x,
                 const float* __restrict__ in_w,
                 const float* __restrict__ in_b,
                 const float* __restrict__ out_w,
                 const float* __restrict__ out_b,
                 const float* __restrict__ cb,
                 float* __restrict__ out)
{
    extern __shared__ float sm[];
    float* R   = sm + SM_R;
    float* W   = sm + SM_W;
    float* ZE  = sm + SM_ZE;
    float* ENC = sm + SM_ENC;
    float* ZQ  = sm + SM_ZQ;
    float* BV  = sm + SM_BV;
    int*   BI  = (int*)(sm + SM_BI);

    const int tid  = threadIdx.x;
    const int lane = tid & 31;
    const int wg   = tid >> 5;
    const int blk  = blockIdx.x;
    const int b    = blk >> 7;
    const int t0   = (blk & 127) << 5;

    const float* xg = x + (size_t)b * DDIM * TT + t0;

    for (int i = tid; i < DDIM*TILE; i += NTHR) {
        int d = i >> 5, t = i & 31;
        R[d*33 + t] = xg[(size_t)d * TT + t];
    }
    __syncthreads();

    for (int q = 0; q < NQ; q++) {
        // ===== Phase A: z_e = in_w @ R  (strict d-ascending, single acc, fma) =====
        const int c0 = wg * 4;
        float acc0 = 0.f, acc1 = 0.f, acc2 = 0.f, acc3 = 0.f;
        const float* inw_q = in_w + (size_t)q * CD * DDIM;

        for (int dc = 0; dc < DDIM; dc += 256) {
            for (int j = tid; j < CD*64; j += NTHR) {
                int c = j >> 6, dq = j & 63;
                ((float4*)W)[j] = ((const float4*)(inw_q + (size_t)c*DDIM + dc))[dq];
            }
            __syncthreads();
            const float* Wr0 = W + (c0+0)*256;
            const float* Wr1 = W + (c0+1)*256;
            const float* Wr2 = W + (c0+2)*256;
            const float* Wr3 = W + (c0+3)*256;
#pragma unroll 4
            for (int dd = 0; dd < 256; dd += 4) {
                float r0 = R[(dc+dd+0)*33 + lane];
                float r1 = R[(dc+dd+1)*33 + lane];
                float r2 = R[(dc+dd+2)*33 + lane];
                float r3 = R[(dc+dd+3)*33 + lane];
                float4 w0 = *(const float4*)(Wr0 + dd);
                float4 w1 = *(const float4*)(Wr1 + dd);
                float4 w2 = *(const float4*)(Wr2 + dd);
                float4 w3 = *(const float4*)(Wr3 + dd);
                acc0 = fmaf(w0.x, r0, acc0); acc0 = fmaf(w0.y, r1, acc0);
                acc0 = fmaf(w0.z, r2, acc0); acc0 = fmaf(w0.w, r3, acc0);
                acc1 = fmaf(w1.x, r0, acc1); acc1 = fmaf(w1.y, r1, acc1);
                acc1 = fmaf(w1.z, r2, acc1); acc1 = fmaf(w1.w, r3, acc1);
                acc2 = fmaf(w2.x, r0, acc2); acc2 = fmaf(w2.y, r1, acc2);
                acc2 = fmaf(w2.z, r2, acc2); acc2 = fmaf(w2.w, r3, acc2);
                acc3 = fmaf(w3.x, r0, acc3); acc3 = fmaf(w3.y, r1, acc3);
                acc3 = fmaf(w3.z, r2, acc3); acc3 = fmaf(w3.w, r3, acc3);
            }
            __syncthreads();
        }
        {
            const float* inb_q = in_b + q*CD;   // bias added AFTER contraction
            ZE[(c0+0)*33 + lane] = acc0 + __ldg(inb_q + c0 + 0);
            ZE[(c0+1)*33 + lane] = acc1 + __ldg(inb_q + c0 + 1);
            ZE[(c0+2)*33 + lane] = acc2 + __ldg(inb_q + c0 + 2);
            ZE[(c0+3)*33 + lane] = acc3 + __ldg(inb_q + c0 + 3);
        }
        __syncthreads();

        // ===== enc = z_e / max(sqrt(sum(z*z)), 1e-12)  (mimic rounding) =====
        if (wg == 0) {
            float n2 = 0.f;
#pragma unroll
            for (int c = 0; c < CD; c++) {
                float z = ZE[c*33 + lane];
                float zz = z * z;
                n2 = n2 + zz;
            }
            float n = fmaxf(sqrtf(n2), 1e-12f);
#pragma unroll
            for (int c = 0; c < CD; c++)
                ENC[c*33 + lane] = ZE[c*33 + lane] / n;
        }
        __syncthreads();

        // ===== Phase B: sim = enc . cbn (c-ascending fma), first-occurrence argmax =====
        {
            float e[CD];
#pragma unroll
            for (int c = 0; c < CD; c++) e[c] = ENC[c*33 + lane];
            float best = -3.0e38f; int bi = 0;
            const float* cbn_q = g_cbn_v5 + (size_t)q * KC * CD;
            for (int kk = 0; kk < 128; kk++) {
                int k = wg*128 + kk;
                const float4* row = (const float4*)(cbn_q + (size_t)k * CD);
                float s = 0.f;
#pragma unroll
                for (int j = 0; j < 8; j++) {
                    float4 v = __ldg(row + j);
                    s = fmaf(e[4*j+0], v.x, s);
                    s = fmaf(e[4*j+1], v.y, s);
                    s = fmaf(e[4*j+2], v.z, s);
                    s = fmaf(e[4*j+3], v.w, s);
                }
                if (s > best) { best = s; bi = k; }
            }
            BV[wg*32 + lane] = best;
            BI[wg*32 + lane] = bi;
        }
        __syncthreads();

        if (wg == 0) {
            float fb = BV[lane]; int fi = BI[lane];
#pragma unroll
            for (int w2 = 1; w2 < 8; w2++) {
                float v = BV[w2*32 + lane];
                if (v > fb) { fb = v; fi = BI[w2*32 + lane]; }
            }
            BI[lane] = fi;
            out[QOFF + ((size_t)q * BB + b) * TT + t0 + lane] = (float)fi;
        }
        __syncthreads();

        // gather z_q = cb[q][idx] (raw codebook rows)
        {
            const float* cb_q = cb + (size_t)q * KC * CD;
            for (int i = tid; i < CD*TILE; i += NTHR) {
                int c = i >> 5, t = i & 31;
                ZQ[c*33 + t] = __ldg(cb_q + (size_t)BI[t] * CD + c);
            }
        }
        __syncthreads();

        // loss partial: uses RAW z_q (reference computes loss before the STE line)
        {
            float lp = 0.f;
            for (int i = tid; i < CD*TILE; i += NTHR) {
                int c = i >> 5, t = i & 31;
                float dv = ZE[c*33 + t] - ZQ[c*33 + t];
                lp = fmaf(dv, dv, lp);
            }
#pragma unroll
            for (int o = 16; o; o >>= 1) lp += __shfl_down_sync(0xffffffffu, lp, o);
            if (lane == 0) BV[wg] = lp;
        }
        __syncthreads();
        if (tid == 0) {
            float s = 0.f;
#pragma unroll
            for (int w2 = 0; w2 < 8; w2++) s += BV[w2];
            g_losspart_v5[q*NBLK + blk] = s;
        }

        // ===== Phase C: residual -= (out_w @ z_q_ste + out_b) =====
        // STE mimicry: forward z_q is fl(z_e + fl(z_q - z_e)), NOT raw z_q.
        {
            float zqc[CD];
#pragma unroll
            for (int c = 0; c < CD; c++) {
                float ze = ZE[c*33 + lane];
                float zq = ZQ[c*33 + lane];
                float dlt = zq - ze;          // rounded difference
                zqc[c] = ze + dlt;            // rounded add-back (~1 ulp off raw zq)
            }
            const float* outw_q = out_w + (size_t)q * DDIM * CD;
            const float* outb_q = out_b + (size_t)q * DDIM;
            for (int dd = 0; dd < 128; dd++) {
                int d = wg*128 + dd;
                const float4* wr = (const float4*)(outw_q + (size_t)d * CD);
                float v = 0.f;
#pragma unroll
                for (int j = 0; j < 8; j++) {
                    float4 w4 = __ldg(wr + j);
                    v = fmaf(w4.x, zqc[4*j+0], v);
                    v = fmaf(w4.y, zqc[4*j+1], v);
                    v = fmaf(w4.z, zqc[4*j+2], v);
                    v = fmaf(w4.w, zqc[4*j+3], v);
                }
                float outv = v + __ldg(outb_q + d);   // bias after contraction
                R[d*33 + lane] = R[d*33 + lane] - outv;
            }
        }
        __syncthreads();
    }

    // quantized_out = x - residual_final
    float* qo = out + (size_t)b * DDIM * TT + t0;
    for (int i = tid; i < DDIM*TILE; i += NTHR) {
        int d = i >> 5, t = i & 31;
        qo[(size_t)d * TT + t] = xg[(size_t)d * TT + t] - R[d*33 + t];
    }
}

// ---------------- Kernel 2: deterministic loss reduction ----------------
__global__ void rvq_loss_v5(float* __restrict__ out) {
    __shared__ float red[NTHR];
    int q = blockIdx.x;
    float s = 0.f;
    for (int i = threadIdx.x; i < NBLK; i += NTHR) s += g_losspart_v5[q*NBLK + i];
    red[threadIdx.x] = s;
    __syncthreads();
    for (int o = NTHR/2; o; o >>= 1) {
        if (threadIdx.x < o) red[threadIdx.x] += red[threadIdx.x + o];
        __syncthreads();
    }
    if (threadIdx.x == 0)
        out[IOFF + q] = 1.25f * red[0] * (1.0f / (float)(BB*CD*TT));
}

// ---------------- launch ----------------
extern "C" void kernel_launch(void* const* d_in, const int* in_sizes, int n_in,
                              void* d_out, int out_size) {
    const float* x     = (const float*)d_in[0];
    const float* in_w  = (const float*)d_in[1];
    const float* in_b  = (const float*)d_in[2];
    const float* out_w = (const float*)d_in[3];
    const float* out_b = (const float*)d_in[4];
    const float* cb    = (const float*)d_in[5];
    float* out = (float*)d_out;

    cudaFuncSetAttribute(rvq_main_v5, cudaFuncAttributeMaxDynamicSharedMemorySize, SMEM_BYTES);

    rvq_normalize_v5<<<(NQ*KC + 127)/128, 128>>>(cb);
    rvq_main_v5<<<NBLK, NTHR, SMEM_BYTES>>>(x, in_w, in_b, out_w, out_b, cb, out);
    rvq_loss_v5<<<NQ, NTHR>>>(out);
}

// round 6
// speedup vs baseline: 1.0557x; 1.0557x over previous
#include <cuda_runtime.h>
#include <math.h>

// ---------------- Problem constants ----------------
#define NQ    8
#define DDIM  1024
#define CD    32
#define KC    1024
#define BB    16
#define TT    4096
#define TILE  32
#define NTHR  512
#define NWARP 16
#define NBLK  ((BB*TT)/TILE)                 // 2048 CTAs
#define QOFF  ((size_t)BB*DDIM*TT)
#define IOFF  (QOFF + (size_t)NQ*BB*TT)

// Shared memory layout (floats)
#define SM_R    0
#define SM_W    (DDIM*33)
#define SM_ZE   (SM_W + CD*256)
#define SM_ENC  (SM_ZE + CD*33)
#define SM_ZQ   (SM_ENC + CD*33)
#define SM_BV   (SM_ZQ + CD*33)
#define SM_BI   (SM_BV + NWARP*32)
#define SM_FLOATS (SM_BI + NWARP*32)
#define SMEM_BYTES (SM_FLOATS * 4)

__device__ float g_cbn_v6[NQ*KC*CD];
__device__ float g_losspart_v6[NQ*NBLK];

// ---------------- Kernel 0: normalize codebook rows ----------------
// jnp mimicry: squares rounded individually, summed strictly ascending with
// plain adds; n = max(sqrt(ss), 1e-12); cbn = v / n with IEEE division.
__global__ void rvq_normalize_v6(const float* __restrict__ cb) {
    int i = blockIdx.x * blockDim.x + threadIdx.x;   // (q*KC + k)
    if (i >= NQ*KC) return;
    const float* src = cb + (size_t)i * CD;
    float v[CD];
    float ss = 0.f;
#pragma unroll
    for (int c = 0; c < CD; c++) {
        v[c] = src[c];
        float vv = v[c] * v[c];
        ss = ss + vv;
    }
    float n = fmaxf(sqrtf(ss), 1e-12f);
    float* dst = g_cbn_v6 + (size_t)i * CD;
#pragma unroll
    for (int c = 0; c < CD; c++) dst[c] = v[c] / n;
}

// ---------------- Kernel 1: fused residual VQ (512 threads) ----------------
__global__ __launch_bounds__(NTHR, 1)
void rvq_main_v6(const float* __restrict__ x,
                 const float* __restrict__ in_w,
                 const float* __restrict__ in_b,
                 const float* __restrict__ out_w,
                 const float* __restrict__ out_b,
                 const float* __restrict__ cb,
                 float* __restrict__ out)
{
    extern __shared__ float sm[];
    float* R   = sm + SM_R;
    float* W   = sm + SM_W;
    float* ZE  = sm + SM_ZE;
    float* ENC = sm + SM_ENC;
    float* ZQ  = sm + SM_ZQ;
    float* BV  = sm + SM_BV;
    int*   BI  = (int*)(sm + SM_BI);

    const int tid  = threadIdx.x;
    const int lane = tid & 31;
    const int wg   = tid >> 5;          // warp id 0..15
    const int blk  = blockIdx.x;
    const int b    = blk >> 7;
    const int t0   = (blk & 127) << 5;

    const float* xg = x + (size_t)b * DDIM * TT + t0;

    for (int i = tid; i < DDIM*TILE; i += NTHR) {
        int d = i >> 5, t = i & 31;
        R[d*33 + t] = xg[(size_t)d * TT + t];
    }
    __syncthreads();

    for (int q = 0; q < NQ; q++) {
        // ===== Phase A: z_e = in_w @ R  (strict d-ascending, single acc, fma) =====
        // warp wg computes channels c0, c0+1 for all 32 columns (lane = t)
        const int c0 = wg * 2;
        float acc0 = 0.f, acc1 = 0.f;
        const float* inw_q = in_w + (size_t)q * CD * DDIM;

        for (int dc = 0; dc < DDIM; dc += 256) {
            for (int j = tid; j < CD*64; j += NTHR) {
                int c = j >> 6, dq = j & 63;
                ((float4*)W)[j] = ((const float4*)(inw_q + (size_t)c*DDIM + dc))[dq];
            }
            __syncthreads();
            const float* Wr0 = W + (c0+0)*256;
            const float* Wr1 = W + (c0+1)*256;
#pragma unroll 8
            for (int dd = 0; dd < 256; dd += 4) {
                float r0 = R[(dc+dd+0)*33 + lane];
                float r1 = R[(dc+dd+1)*33 + lane];
                float r2 = R[(dc+dd+2)*33 + lane];
                float r3 = R[(dc+dd+3)*33 + lane];
                float4 w0 = *(const float4*)(Wr0 + dd);
                float4 w1 = *(const float4*)(Wr1 + dd);
                // ascending within the 4-group: d+0, d+1, d+2, d+3
                acc0 = fmaf(w0.x, r0, acc0); acc0 = fmaf(w0.y, r1, acc0);
                acc0 = fmaf(w0.z, r2, acc0); acc0 = fmaf(w0.w, r3, acc0);
                acc1 = fmaf(w1.x, r0, acc1); acc1 = fmaf(w1.y, r1, acc1);
                acc1 = fmaf(w1.z, r2, acc1); acc1 = fmaf(w1.w, r3, acc1);
            }
            __syncthreads();
        }
        {
            const float* inb_q = in_b + q*CD;   // bias added AFTER contraction
            ZE[(c0+0)*33 + lane] = acc0 + __ldg(inb_q + c0 + 0);
            ZE[(c0+1)*33 + lane] = acc1 + __ldg(inb_q + c0 + 1);
        }
        __syncthreads();

        // ===== enc = z_e / max(sqrt(sum(z*z)), 1e-12)  (mimic rounding) =====
        if (wg == 0) {
            float n2 = 0.f;
#pragma unroll
            for (int c = 0; c < CD; c++) {
                float z = ZE[c*33 + lane];
                float zz = z * z;
                n2 = n2 + zz;
            }
            float n = fmaxf(sqrtf(n2), 1e-12f);
#pragma unroll
            for (int c = 0; c < CD; c++)
                ENC[c*33 + lane] = ZE[c*33 + lane] / n;
        }
        __syncthreads();

        // ===== Phase B: sim = enc . cbn (c-ascending fma), first-occurrence argmax =====
        // warp wg scans codes [wg*64, wg*64+64); lane owns column t = lane.
        {
            float e[CD];
#pragma unroll
            for (int c = 0; c < CD; c++) e[c] = ENC[c*33 + lane];
            float best = -3.0e38f; int bi = 0;
            const float* cbn_q = g_cbn_v6 + (size_t)q * KC * CD;
            for (int kk = 0; kk < 64; kk++) {
                int k = wg*64 + kk;
                const float4* row = (const float4*)(cbn_q + (size_t)k * CD);
                float s = 0.f;
#pragma unroll
                for (int j = 0; j < 8; j++) {
                    float4 v = __ldg(row + j);
                    s = fmaf(e[4*j+0], v.x, s);
                    s = fmaf(e[4*j+1], v.y, s);
                    s = fmaf(e[4*j+2], v.z, s);
                    s = fmaf(e[4*j+3], v.w, s);
                }
                if (s > best) { best = s; bi = k; }   // strict >: first occurrence
            }
            BV[wg*32 + lane] = best;
            BI[wg*32 + lane] = bi;
        }
        __syncthreads();

        // cross-warp merge ascending (code ranges ascending -> first-occurrence kept)
        if (wg == 0) {
            float fb = BV[lane]; int fi = BI[lane];
#pragma unroll
            for (int w2 = 1; w2 < NWARP; w2++) {
                float v = BV[w2*32 + lane];
                if (v > fb) { fb = v; fi = BI[w2*32 + lane]; }
            }
            BI[lane] = fi;
            out[QOFF + ((size_t)q * BB + b) * TT + t0 + lane] = (float)fi;
        }
        __syncthreads();

        // gather z_q = cb[q][idx] (raw codebook rows)
        {
            const float* cb_q = cb + (size_t)q * KC * CD;
            for (int i = tid; i < CD*TILE; i += NTHR) {
                int c = i >> 5, t = i & 31;
                ZQ[c*33 + t] = __ldg(cb_q + (size_t)BI[t] * CD + c);
            }
        }
        __syncthreads();

        // loss partial: uses RAW z_q (reference computes loss before the STE line)
        {
            float lp = 0.f;
            for (int i = tid; i < CD*TILE; i += NTHR) {
                int c = i >> 5, t = i & 31;
                float dv = ZE[c*33 + t] - ZQ[c*33 + t];
                lp = fmaf(dv, dv, lp);
            }
#pragma unroll
            for (int o = 16; o; o >>= 1) lp += __shfl_down_sync(0xffffffffu, lp, o);
            if (lane == 0) BV[wg] = lp;
        }
        __syncthreads();
        if (tid == 0) {
            float s = 0.f;
#pragma unroll
            for (int w2 = 0; w2 < NWARP; w2++) s += BV[w2];
            g_losspart_v6[q*NBLK + blk] = s;
        }

        // ===== Phase C: residual -= (out_w @ z_q_ste + out_b) =====
        // STE mimicry: forward z_q is fl(z_e + fl(z_q - z_e)), NOT raw z_q.
        // warp wg handles d in [wg*64, wg*64+64); lane owns column t = lane.
        {
            float zqc[CD];
#pragma unroll
            for (int c = 0; c < CD; c++) {
                float ze = ZE[c*33 + lane];
                float zq = ZQ[c*33 + lane];
                float dlt = zq - ze;          // rounded difference
                zqc[c] = ze + dlt;            // rounded add-back (~1 ulp off raw zq)
            }
            const float* outw_q = out_w + (size_t)q * DDIM * CD;
            const float* outb_q = out_b + (size_t)q * DDIM;
            for (int dd = 0; dd < 64; dd++) {
                int d = wg*64 + dd;
                const float4* wr = (const float4*)(outw_q + (size_t)d * CD);
                float v = 0.f;
#pragma unroll
                for (int j = 0; j < 8; j++) {
                    float4 w4 = __ldg(wr + j);
                    v = fmaf(w4.x, zqc[4*j+0], v);
                    v = fmaf(w4.y, zqc[4*j+1], v);
                    v = fmaf(w4.z, zqc[4*j+2], v);
                    v = fmaf(w4.w, zqc[4*j+3], v);
                }
                float outv = v + __ldg(outb_q + d);   // bias after contraction
                R[d*33 + lane] = R[d*33 + lane] - outv;
            }
        }
        __syncthreads();
    }

    // quantized_out = x - residual_final
    float* qo = out + (size_t)b * DDIM * TT + t0;
    for (int i = tid; i < DDIM*TILE; i += NTHR) {
        int d = i >> 5, t = i & 31;
        qo[(size_t)d * TT + t] = xg[(size_t)d * TT + t] - R[d*33 + t];
    }
}

// ---------------- Kernel 2: deterministic loss reduction ----------------
__global__ void rvq_loss_v6(float* __restrict__ out) {
    __shared__ float red[256];
    int q = blockIdx.x;
    float s = 0.f;
    for (int i = threadIdx.x; i < NBLK; i += 256) s += g_losspart_v6[q*NBLK + i];
    red[threadIdx.x] = s;
    __syncthreads();
    for (int o = 128; o; o >>= 1) {
        if (threadIdx.x < o) red[threadIdx.x] += red[threadIdx.x + o];
        __syncthreads();
    }
    if (threadIdx.x == 0)
        out[IOFF + q] = 1.25f * red[0] * (1.0f / (float)(BB*CD*TT));
}

// ---------------- launch ----------------
extern "C" void kernel_launch(void* const* d_in, const int* in_sizes, int n_in,
                              void* d_out, int out_size) {
    const float* x     = (const float*)d_in[0];
    const float* in_w  = (const float*)d_in[1];
    const float* in_b  = (const float*)d_in[2];
    const float* out_w = (const float*)d_in[3];
    const float* out_b = (const float*)d_in[4];
    const float* cb    = (const float*)d_in[5];
    float* out = (float*)d_out;

    cudaFuncSetAttribute(rvq_main_v6, cudaFuncAttributeMaxDynamicSharedMemorySize, SMEM_BYTES);

    rvq_normalize_v6<<<(NQ*KC + 127)/128, 128>>>(cb);
    rvq_main_v6<<<NBLK, NTHR, SMEM_BYTES>>>(x, in_w, in_b, out_w, out_b, cb, out);
    rvq_loss_v6<<<NQ, 256>>>(out);
}

// round 8
// speedup vs baseline: 1.1496x; 1.0890x over previous
#include <cuda_runtime.h>
#include <math.h>

// ---------------- Problem constants ----------------
#define NQ    8
#define DDIM  1024
#define CD    32
#define KC    1024
#define BB    16
#define TT    4096
#define TILE  32
#define NTHR  512
#define NWARP 16
#define NCTA  148
#define NTILES ((BB*TT)/TILE)                // 2048 tiles
#define QOFF  ((size_t)BB*DDIM*TT)
#define IOFF  (QOFF + (size_t)NQ*BB*TT)

// Shared memory layout (floats)
#define SM_R    0
#define SM_W    (DDIM*33)                    // two 32x256 buffers (16384 floats)
#define SM_ZE   (SM_W + 2*CD*256)
#define SM_ENC  (SM_ZE + CD*33)
#define SM_ZQ   (SM_ENC + CD*33)
#define SM_BV   (SM_ZQ + CD*33)
#define SM_BI   (SM_BV + NWARP*32)
#define SM_FLOATS (SM_BI + NWARP*32)
#define SMEM_BYTES (SM_FLOATS * 4)           // 217472 bytes

__device__ float g_cbn_v7[NQ*KC*CD];
__device__ float g_losspart_v7[NQ*NTILES];
__device__ int   g_tick_v7;                  // monotonic ticket barrier (graph-safe)

// Device-wide barrier: all NCTA CTAs are resident (1/SM), so spinning is safe.
// Monotonic ticket => no reset needed across graph replays.
__device__ __forceinline__ void grid_barrier(int tid) {
    __syncthreads();
    if (tid == 0) {
        __threadfence();
        int t = atomicAdd(&g_tick_v7, 1);
        int target = (t / NCTA + 1) * NCTA;
        while (*(volatile int*)&g_tick_v7 < target) { }
        __threadfence();
    }
    __syncthreads();
}

// ---------------- Single persistent kernel ----------------
__global__ __launch_bounds__(NTHR, 1)
void rvq_persist_v7(const float* __restrict__ x,
                    const float* __restrict__ in_w,
                    const float* __restrict__ in_b,
                    const float* __restrict__ out_w,
                    const float* __restrict__ out_b,
                    const float* __restrict__ cb,
                    float* __restrict__ out)
{
    extern __shared__ float sm[];
    float* R   = sm + SM_R;
    float* W0  = sm + SM_W;                  // buffer 0
    float* W1  = sm + SM_W + CD*256;         // buffer 1
    float* ZE  = sm + SM_ZE;
    float* ENC = sm + SM_ENC;
    float* ZQ  = sm + SM_ZQ;
    float* BV  = sm + SM_BV;
    int*   BI  = (int*)(sm + SM_BI);

    const int tid  = threadIdx.x;
    const int lane = tid & 31;
    const int wg   = tid >> 5;               // warp id 0..15
    const int bid  = blockIdx.x;

    // ===== Prologue: normalize codebook rows (jnp rounding mimicry) =====
    {
        int gid = bid * NTHR + tid;          // 75776 threads >= 8192 rows
        if (gid < NQ*KC) {
            const float* src = cb + (size_t)gid * CD;
            float v[CD];
            float ss = 0.f;
#pragma unroll
            for (int c = 0; c < CD; c++) {
                v[c] = src[c];
                float vv = v[c] * v[c];      // rounded square
                ss = ss + vv;                // ascending plain add
            }
            float n = fmaxf(sqrtf(ss), 1e-12f);
            float* dst = g_cbn_v7 + (size_t)gid * CD;
#pragma unroll
            for (int c = 0; c < CD; c++) dst[c] = v[c] / n;   // IEEE division
            __threadfence();
        }
    }
    grid_barrier(tid);

    // ===== Tile loop =====
    for (int blk = bid; blk < NTILES; blk += NCTA) {
        const int b  = blk >> 7;
        const int t0 = (blk & 127) << 5;
        const float* xg = x + (size_t)b * DDIM * TT + t0;

        for (int i = tid; i < DDIM*TILE; i += NTHR) {
            int d = i >> 5, t = i & 31;
            R[d*33 + t] = xg[(size_t)d * TT + t];
        }
        __syncthreads();

        for (int q = 0; q < NQ; q++) {
            const float* inw_q = in_w + (size_t)q * CD * DDIM;

            // stage chunk 0 into W0 (stager warps 8..15)
            if (wg >= 8) {
                for (int j = tid - 256; j < CD*64; j += 256) {
                    int c = j >> 6, dq = j & 63;
                    ((float4*)W0)[j] = ((const float4*)(inw_q + (size_t)c*DDIM))[dq];
                }
            }
            __syncthreads();

            // ===== Phase A: z_e = in_w @ R (v5-bitwise: 4ch/warp, warps 0..7) =====
            const int c0 = (wg & 7) * 4;
            float acc0 = 0.f, acc1 = 0.f, acc2 = 0.f, acc3 = 0.f;

            for (int ci = 0; ci < 4; ci++) {
                if (wg < 8) {
                    const int dc = ci * 256;
                    float* Wb = (ci & 1) ? W1 : W0;
                    const float* Wr0 = Wb + (c0+0)*256;
                    const float* Wr1 = Wb + (c0+1)*256;
                    const float* Wr2 = Wb + (c0+2)*256;
                    const float* Wr3 = Wb + (c0+3)*256;
#pragma unroll 4
                    for (int dd = 0; dd < 256; dd += 4) {
                        float r0 = R[(dc+dd+0)*33 + lane];
                        float r1 = R[(dc+dd+1)*33 + lane];
                        float r2 = R[(dc+dd+2)*33 + lane];
                        float r3 = R[(dc+dd+3)*33 + lane];
                        float4 w0 = *(const float4*)(Wr0 + dd);
                        float4 w1 = *(const float4*)(Wr1 + dd);
                        float4 w2 = *(const float4*)(Wr2 + dd);
                        float4 w3 = *(const float4*)(Wr3 + dd);
                        // strict ascending d within group (v5 order)
                        acc0 = fmaf(w0.x, r0, acc0); acc0 = fmaf(w0.y, r1, acc0);
                        acc0 = fmaf(w0.z, r2, acc0); acc0 = fmaf(w0.w, r3, acc0);
                        acc1 = fmaf(w1.x, r0, acc1); acc1 = fmaf(w1.y, r1, acc1);
                        acc1 = fmaf(w1.z, r2, acc1); acc1 = fmaf(w1.w, r3, acc1);
                        acc2 = fmaf(w2.x, r0, acc2); acc2 = fmaf(w2.y, r1, acc2);
                        acc2 = fmaf(w2.z, r2, acc2); acc2 = fmaf(w2.w, r3, acc2);
                        acc3 = fmaf(w3.x, r0, acc3); acc3 = fmaf(w3.y, r1, acc3);
                        acc3 = fmaf(w3.z, r2, acc3); acc3 = fmaf(w3.w, r3, acc3);
                    }
                } else if (ci < 3) {
                    // stage chunk ci+1 into the other buffer
                    const int dcn = (ci + 1) * 256;
                    float* Wn = ((ci + 1) & 1) ? W1 : W0;
                    for (int j = tid - 256; j < CD*64; j += 256) {
                        int c = j >> 6, dq = j & 63;
                        ((float4*)Wn)[j] = ((const float4*)(inw_q + (size_t)c*DDIM + dcn))[dq];
                    }
                }
                __syncthreads();
            }
            if (wg < 8) {
                const float* inb_q = in_b + q*CD;    // bias AFTER contraction
                ZE[(c0+0)*33 + lane] = acc0 + __ldg(inb_q + c0 + 0);
                ZE[(c0+1)*33 + lane] = acc1 + __ldg(inb_q + c0 + 1);
                ZE[(c0+2)*33 + lane] = acc2 + __ldg(inb_q + c0 + 2);
                ZE[(c0+3)*33 + lane] = acc3 + __ldg(inb_q + c0 + 3);
            }
            __syncthreads();

            // ===== enc = z_e / max(sqrt(sum(z*z)), 1e-12) (warp 0, v6-bitwise) =====
            if (wg == 0) {
                float n2 = 0.f;
#pragma unroll
                for (int c = 0; c < CD; c++) {
                    float z = ZE[c*33 + lane];
                    float zz = z * z;
                    n2 = n2 + zz;
                }
                float n = fmaxf(sqrtf(n2), 1e-12f);
#pragma unroll
                for (int c = 0; c < CD; c++)
                    ENC[c*33 + lane] = ZE[c*33 + lane] / n;
            }
            __syncthreads();

            // ===== Phase B: sim + argmax (v6-bitwise: 64 codes/warp) =====
            {
                float e[CD];
#pragma unroll
                for (int c = 0; c < CD; c++) e[c] = ENC[c*33 + lane];
                float best = -3.0e38f; int bi = 0;
                const float* cbn_q = g_cbn_v7 + (size_t)q * KC * CD;
                for (int kk = 0; kk < 64; kk++) {
                    int k = wg*64 + kk;
                    const float4* row = (const float4*)(cbn_q + (size_t)k * CD);
                    float s = 0.f;
#pragma unroll
                    for (int j = 0; j < 8; j++) {
                        float4 v = __ldg(row + j);
                        s = fmaf(e[4*j+0], v.x, s);
                        s = fmaf(e[4*j+1], v.y, s);
                        s = fmaf(e[4*j+2], v.z, s);
                        s = fmaf(e[4*j+3], v.w, s);
                    }
                    if (s > best) { best = s; bi = k; }   // first occurrence
                }
                BV[wg*32 + lane] = best;
                BI[wg*32 + lane] = bi;
            }
            __syncthreads();

            if (wg == 0) {
                float fb = BV[lane]; int fi = BI[lane];
#pragma unroll
                for (int w2 = 1; w2 < NWARP; w2++) {
                    float v = BV[w2*32 + lane];
                    if (v > fb) { fb = v; fi = BI[w2*32 + lane]; }
                }
                BI[lane] = fi;
                out[QOFF + ((size_t)q * BB + b) * TT + t0 + lane] = (float)fi;
            }
            __syncthreads();

            // gather z_q = cb[q][idx]
            {
                const float* cb_q = cb + (size_t)q * KC * CD;
                for (int i = tid; i < CD*TILE; i += NTHR) {
                    int c = i >> 5, t = i & 31;
                    ZQ[c*33 + t] = __ldg(cb_q + (size_t)BI[t] * CD + c);
                }
            }
            __syncthreads();

            // loss partial (raw z_q; v6-bitwise per-thread chain)
            {
                float lp = 0.f;
                for (int i = tid; i < CD*TILE; i += NTHR) {
                    int c = i >> 5, t = i & 31;
                    float dv = ZE[c*33 + t] - ZQ[c*33 + t];
                    lp = fmaf(dv, dv, lp);
                }
#pragma unroll
                for (int o = 16; o; o >>= 1) lp += __shfl_down_sync(0xffffffffu, lp, o);
                if (lane == 0) BV[wg] = lp;
            }
            __syncthreads();
            if (tid == 0) {
                float s = 0.f;
#pragma unroll
                for (int w2 = 0; w2 < NWARP; w2++) s += BV[w2];
                g_losspart_v7[q*NTILES + blk] = s;
            }

            // ===== Phase C: residual -= (out_w @ z_q_ste + out_b) (v6-bitwise) =====
            {
                float zqc[CD];
#pragma unroll
                for (int c = 0; c < CD; c++) {
                    float ze = ZE[c*33 + lane];
                    float zq = ZQ[c*33 + lane];
                    float dlt = zq - ze;      // STE: fl(z_e + fl(z_q - z_e))
                    zqc[c] = ze + dlt;
                }
                const float* outw_q = out_w + (size_t)q * DDIM * CD;
                const float* outb_q = out_b + (size_t)q * DDIM;
                for (int dd = 0; dd < 64; dd++) {
                    int d = wg*64 + dd;
                    const float4* wr = (const float4*)(outw_q + (size_t)d * CD);
                    float v = 0.f;
#pragma unroll
                    for (int j = 0; j < 8; j++) {
                        float4 w4 = __ldg(wr + j);
                        v = fmaf(w4.x, zqc[4*j+0], v);
                        v = fmaf(w4.y, zqc[4*j+1], v);
                        v = fmaf(w4.z, zqc[4*j+2], v);
                        v = fmaf(w4.w, zqc[4*j+3], v);
                    }
                    float outv = v + __ldg(outb_q + d);   // bias after
                    R[d*33 + lane] = R[d*33 + lane] - outv;
                }
            }
            __syncthreads();
        }

        // quantized_out = x - residual_final
        float* qo = out + (size_t)b * DDIM * TT + t0;
        for (int i = tid; i < DDIM*TILE; i += NTHR) {
            int d = i >> 5, t = i & 31;
            qo[(size_t)d * TT + t] = xg[(size_t)d * TT + t] - R[d*33 + t];
        }
        __syncthreads();
    }

    // ===== Epilogue: deterministic loss reduction (CTAs 0..7) =====
    if (tid == 0) __threadfence();
    grid_barrier(tid);
    if (bid < NQ) {
        float* red = sm;                      // reuse smem
        int q = bid;
        float s = 0.f;
        for (int i = tid; i < NTILES; i += NTHR) s += g_losspart_v7[q*NTILES + i];
        red[tid] = s;
        __syncthreads();
        for (int o = NTHR/2; o; o >>= 1) {
            if (tid < o) red[tid] += red[tid + o];
            __syncthreads();
        }
        if (tid == 0)
            out[IOFF + q] = 1.25f * red[0] * (1.0f / (float)(BB*CD*TT));
    }
}

// ---------------- launch: ONE kernel (ncu must capture it) ----------------
extern "C" void kernel_launch(void* const* d_in, const int* in_sizes, int n_in,
                              void* d_out, int out_size) {
    const float* x     = (const float*)d_in[0];
    const float* in_w  = (const float*)d_in[1];
    const float* in_b  = (const float*)d_in[2];
    const float* out_w = (const float*)d_in[3];
    const float* out_b = (const float*)d_in[4];
    const float* cb    = (const float*)d_in[5];
    float* out = (float*)d_out;

    cudaFuncSetAttribute(rvq_persist_v7, cudaFuncAttributeMaxDynamicSharedMemorySize, SMEM_BYTES);
    rvq_persist_v7<<<NCTA, NTHR, SMEM_BYTES>>>(x, in_w, in_b, out_w, out_b, cb, out);
}

// round 10
// speedup vs baseline: 1.2651x; 1.1005x over previous
#include <cuda_runtime.h>
#include <math.h>

// ---------------- Problem constants ----------------
#define NQ    8
#define DDIM  1024
#define CD    32
#define KC    1024
#define BB    16
#define TT    4096
#define TILE  32
#define NTHR  512
#define NWARP 16
#define NCTA  148
#define NTILES ((BB*TT)/TILE)                // 2048 tiles
#define QOFF  ((size_t)BB*DDIM*TT)
#define IOFF  (QOFF + (size_t)NQ*BB*TT)

// Shared memory layout (floats)
#define SM_R     0
#define SM_W     (DDIM*33)                   // 33792 (two 32x256 buffers)
#define SM_ZE    (SM_W + 2*CD*256)           // 50176
#define SM_ZQ    (SM_ZE + CD*33)             // 51232
#define SM_ENCT  (SM_ZQ + CD*33)             // 52288  ENC transposed [t][36]
#define SM_ZQST  (SM_ENCT + 32*36)           // 53440  STE z_q transposed [t][36]
#define SM_BV    (SM_ZQST + 32*36)           // 54592
#define SM_BI    (SM_BV + NWARP*32)          // 55104
#define SM_FLOATS (SM_BI + NWARP*32)         // 55616
#define SMEM_BYTES (SM_FLOATS * 4)           // 222464 bytes

__device__ float g_cbn_v8[NQ*KC*CD];
__device__ float g_losspart_v8[NQ*NTILES];
__device__ int   g_tick_v8;                  // monotonic ticket barrier

__device__ __forceinline__ void grid_barrier(int tid) {
    __syncthreads();
    if (tid == 0) {
        __threadfence();
        int t = atomicAdd(&g_tick_v8, 1);
        int target = (t / NCTA + 1) * NCTA;
        while (*(volatile int*)&g_tick_v8 < target) { }
        __threadfence();
    }
    __syncthreads();
}

// monotone, equality-preserving float->uint32 map (finite inputs)
__device__ __forceinline__ unsigned f2ord(float f) {
    int b = __float_as_int(f);
    return (b >= 0) ? ((unsigned)b | 0x80000000u) : ~(unsigned)b;
}

// ---------------- Single persistent kernel ----------------
__global__ __launch_bounds__(NTHR, 1)
void rvq_persist_v8(const float* __restrict__ x,
                    const float* __restrict__ in_w,
                    const float* __restrict__ in_b,
                    const float* __restrict__ out_w,
                    const float* __restrict__ out_b,
                    const float* __restrict__ cb,
                    float* __restrict__ out)
{
    extern __shared__ float sm[];
    float* R    = sm + SM_R;
    float* W0   = sm + SM_W;
    float* W1   = sm + SM_W + CD*256;
    float* ZE   = sm + SM_ZE;
    float* ZQ   = sm + SM_ZQ;
    float* ENCT = sm + SM_ENCT;
    float* ZQST = sm + SM_ZQST;
    float* BV   = sm + SM_BV;
    int*   BI   = (int*)(sm + SM_BI);

    const int tid  = threadIdx.x;
    const int lane = tid & 31;
    const int wg   = tid >> 5;               // 0..15
    const int bid  = blockIdx.x;

    // ===== Prologue: normalize codebook rows (jnp rounding mimicry) =====
    {
        int gid = bid * NTHR + tid;
        if (gid < NQ*KC) {
            const float* src = cb + (size_t)gid * CD;
            float v[CD];
            float ss = 0.f;
#pragma unroll
            for (int c = 0; c < CD; c++) {
                v[c] = src[c];
                float vv = v[c] * v[c];      // rounded square
                ss = ss + vv;                // ascending plain add
            }
            float n = fmaxf(sqrtf(ss), 1e-12f);
            float* dst = g_cbn_v8 + (size_t)gid * CD;
#pragma unroll
            for (int c = 0; c < CD; c++) dst[c] = v[c] / n;   // IEEE division
            __threadfence();
        }
    }
    grid_barrier(tid);

    // ===== Tile loop =====
    for (int blk = bid; blk < NTILES; blk += NCTA) {
        const int b  = blk >> 7;
        const int t0 = (blk & 127) << 5;
        const float* xg = x + (size_t)b * DDIM * TT + t0;

        for (int i = tid; i < DDIM*TILE; i += NTHR) {
            int d = i >> 5, t = i & 31;
            R[d*33 + t] = xg[(size_t)d * TT + t];
        }
        __syncthreads();

        for (int q = 0; q < NQ; q++) {
            const float* inw_q = in_w + (size_t)q * CD * DDIM;

            // stage chunk 0 into W0 (warps 8..15)
            if (wg >= 8) {
                for (int j = tid - 256; j < CD*64; j += 256) {
                    int c = j >> 6, dq = j & 63;
                    ((float4*)W0)[j] = ((const float4*)(inw_q + (size_t)c*DDIM))[dq];
                }
            }
            __syncthreads();

            // ===== Phase A: z_e = in_w @ R (v5-bitwise; warps 0..7 compute) =====
            const int c0 = (wg & 7) * 4;
            float acc0 = 0.f, acc1 = 0.f, acc2 = 0.f, acc3 = 0.f;

            for (int ci = 0; ci < 4; ci++) {
                if (wg < 8) {
                    const int dc = ci * 256;
                    float* Wb = (ci & 1) ? W1 : W0;
                    const float* Wr0 = Wb + (c0+0)*256;
                    const float* Wr1 = Wb + (c0+1)*256;
                    const float* Wr2 = Wb + (c0+2)*256;
                    const float* Wr3 = Wb + (c0+3)*256;
#pragma unroll 4
                    for (int dd = 0; dd < 256; dd += 4) {
                        float r0 = R[(dc+dd+0)*33 + lane];
                        float r1 = R[(dc+dd+1)*33 + lane];
                        float r2 = R[(dc+dd+2)*33 + lane];
                        float r3 = R[(dc+dd+3)*33 + lane];
                        float4 w0 = *(const float4*)(Wr0 + dd);
                        float4 w1 = *(const float4*)(Wr1 + dd);
                        float4 w2 = *(const float4*)(Wr2 + dd);
                        float4 w3 = *(const float4*)(Wr3 + dd);
                        acc0 = fmaf(w0.x, r0, acc0); acc0 = fmaf(w0.y, r1, acc0);
                        acc0 = fmaf(w0.z, r2, acc0); acc0 = fmaf(w0.w, r3, acc0);
                        acc1 = fmaf(w1.x, r0, acc1); acc1 = fmaf(w1.y, r1, acc1);
                        acc1 = fmaf(w1.z, r2, acc1); acc1 = fmaf(w1.w, r3, acc1);
                        acc2 = fmaf(w2.x, r0, acc2); acc2 = fmaf(w2.y, r1, acc2);
                        acc2 = fmaf(w2.z, r2, acc2); acc2 = fmaf(w2.w, r3, acc2);
                        acc3 = fmaf(w3.x, r0, acc3); acc3 = fmaf(w3.y, r1, acc3);
                        acc3 = fmaf(w3.z, r2, acc3); acc3 = fmaf(w3.w, r3, acc3);
                    }
                } else if (ci < 3) {
                    const int dcn = (ci + 1) * 256;
                    float* Wn = ((ci + 1) & 1) ? W1 : W0;
                    for (int j = tid - 256; j < CD*64; j += 256) {
                        int c = j >> 6, dq = j & 63;
                        ((float4*)Wn)[j] = ((const float4*)(inw_q + (size_t)c*DDIM + dcn))[dq];
                    }
                }
                __syncthreads();
            }
            if (wg < 8) {
                const float* inb_q = in_b + q*CD;
                ZE[(c0+0)*33 + lane] = acc0 + __ldg(inb_q + c0 + 0);
                ZE[(c0+1)*33 + lane] = acc1 + __ldg(inb_q + c0 + 1);
                ZE[(c0+2)*33 + lane] = acc2 + __ldg(inb_q + c0 + 2);
                ZE[(c0+3)*33 + lane] = acc3 + __ldg(inb_q + c0 + 3);
            }
            __syncthreads();

            // ===== enc (v6-bitwise values) written TRANSPOSED: ENCT[t*36 + c] =====
            if (wg == 0) {
                float n2 = 0.f;
#pragma unroll
                for (int c = 0; c < CD; c++) {
                    float z = ZE[c*33 + lane];
                    float zz = z * z;
                    n2 = n2 + zz;
                }
                float n = fmaxf(sqrtf(n2), 1e-12f);
#pragma unroll
                for (int c = 0; c < CD; c++)
                    ENCT[lane*36 + c] = ZE[c*33 + lane] / n;   // IEEE division
            }
            __syncthreads();

            // ===== Phase B: lane = code. Coalesced row loads, broadcast enc =====
            {
                const float* cbn_q = g_cbn_v8 + (size_t)q * KC * CD;
                float bestv = 0.f; int bestk = 0;   // owned by lane t for column t
#pragma unroll
                for (int batch = 0; batch < 2; batch++) {
                    int k = wg*64 + batch*32 + lane;
                    const float4* rp = (const float4*)(cbn_q + (size_t)k * CD);
                    float4 rr0 = __ldg(rp+0), rr1 = __ldg(rp+1);
                    float4 rr2 = __ldg(rp+2), rr3 = __ldg(rp+3);
                    float4 rr4 = __ldg(rp+4), rr5 = __ldg(rp+5);
                    float4 rr6 = __ldg(rp+6), rr7 = __ldg(rp+7);
#pragma unroll 4
                    for (int t = 0; t < TILE; t++) {
                        const float4* ev = (const float4*)(ENCT + t*36);
                        float4 e0 = ev[0], e1 = ev[1], e2 = ev[2], e3 = ev[3];
                        float4 e4 = ev[4], e5 = ev[5], e6 = ev[6], e7 = ev[7];
                        float s = 0.f;   // ascending-c single-accumulator chain
                        s = fmaf(rr0.x,e0.x,s); s = fmaf(rr0.y,e0.y,s);
                        s = fmaf(rr0.z,e0.z,s); s = fmaf(rr0.w,e0.w,s);
                        s = fmaf(rr1.x,e1.x,s); s = fmaf(rr1.y,e1.y,s);
                        s = fmaf(rr1.z,e1.z,s); s = fmaf(rr1.w,e1.w,s);
                        s = fmaf(rr2.x,e2.x,s); s = fmaf(rr2.y,e2.y,s);
                        s = fmaf(rr2.z,e2.z,s); s = fmaf(rr2.w,e2.w,s);
                        s = fmaf(rr3.x,e3.x,s); s = fmaf(rr3.y,e3.y,s);
                        s = fmaf(rr3.z,e3.z,s); s = fmaf(rr3.w,e3.w,s);
                        s = fmaf(rr4.x,e4.x,s); s = fmaf(rr4.y,e4.y,s);
                        s = fmaf(rr4.z,e4.z,s); s = fmaf(rr4.w,e4.w,s);
                        s = fmaf(rr5.x,e5.x,s); s = fmaf(rr5.y,e5.y,s);
                        s = fmaf(rr5.z,e5.z,s); s = fmaf(rr5.w,e5.w,s);
                        s = fmaf(rr6.x,e6.x,s); s = fmaf(rr6.y,e6.y,s);
                        s = fmaf(rr6.z,e6.z,s); s = fmaf(rr6.w,e6.w,s);
                        s = fmaf(rr7.x,e7.x,s); s = fmaf(rr7.y,e7.y,s);
                        s = fmaf(rr7.z,e7.z,s); s = fmaf(rr7.w,e7.w,s);
                        // exact first-occurrence argmax across the 32 codes
                        unsigned u = f2ord(s);
                        unsigned m = __reduce_max_sync(0xffffffffu, u);
                        unsigned eq = __ballot_sync(0xffffffffu, u == m);
                        int l = __ffs(eq) - 1;            // lowest lane = lowest k
                        float sb = __shfl_sync(0xffffffffu, s, l);
                        int   kb = wg*64 + batch*32 + l;
                        if (lane == t) {
                            if (batch == 0) { bestv = sb; bestk = kb; }
                            else if (sb > bestv) { bestv = sb; bestk = kb; } // tie->lower k
                        }
                    }
                }
                BV[wg*32 + lane] = bestv;   // lane t holds column t
                BI[wg*32 + lane] = bestk;
            }
            __syncthreads();

            // cross-warp merge (ascending code ranges; strict > keeps lowest k)
            if (wg == 0) {
                float fb = BV[lane]; int fi = BI[lane];
#pragma unroll
                for (int w2 = 1; w2 < NWARP; w2++) {
                    float v = BV[w2*32 + lane];
                    if (v > fb) { fb = v; fi = BI[w2*32 + lane]; }
                }
                BI[lane] = fi;
                out[QOFF + ((size_t)q * BB + b) * TT + t0 + lane] = (float)fi;
            }
            __syncthreads();

            // gather z_q = cb[q][idx]
            {
                const float* cb_q = cb + (size_t)q * KC * CD;
                for (int i = tid; i < CD*TILE; i += NTHR) {
                    int c = i >> 5, t = i & 31;
                    ZQ[c*33 + t] = __ldg(cb_q + (size_t)BI[t] * CD + c);
                }
            }
            __syncthreads();

            // loss partial (raw z_q; v6-bitwise chain) + STE transposed build
            {
                float lp = 0.f;
                for (int i = tid; i < CD*TILE; i += NTHR) {
                    int c = i >> 5, t = i & 31;
                    float ze = ZE[c*33 + t];
                    float zq = ZQ[c*33 + t];
                    float dv = ze - zq;
                    lp = fmaf(dv, dv, lp);
                    float dlt = zq - ze;          // STE: fl(z_e + fl(z_q - z_e))
                    ZQST[t*36 + c] = ze + dlt;
                }
#pragma unroll
                for (int o = 16; o; o >>= 1) lp += __shfl_down_sync(0xffffffffu, lp, o);
                if (lane == 0) BV[wg] = lp;
            }
            __syncthreads();
            if (tid == 0) {
                float s = 0.f;
#pragma unroll
                for (int w2 = 0; w2 < NWARP; w2++) s += BV[w2];
                g_losspart_v8[q*NTILES + blk] = s;
            }

            // ===== Phase C: lane = row d. Coalesced out_w rows, broadcast zq =====
            {
                const float* outw_q = out_w + (size_t)q * DDIM * CD;
                const float* outb_q = out_b + (size_t)q * DDIM;
#pragma unroll
                for (int batch = 0; batch < 2; batch++) {
                    int d = wg*64 + batch*32 + lane;
                    const float4* wp = (const float4*)(outw_q + (size_t)d * CD);
                    float4 w0 = __ldg(wp+0), w1 = __ldg(wp+1);
                    float4 w2 = __ldg(wp+2), w3 = __ldg(wp+3);
                    float4 w4 = __ldg(wp+4), w5 = __ldg(wp+5);
                    float4 w6 = __ldg(wp+6), w7 = __ldg(wp+7);
                    float ob = __ldg(outb_q + d);
#pragma unroll 4
                    for (int t = 0; t < TILE; t++) {
                        const float4* zv = (const float4*)(ZQST + t*36);
                        float4 z0 = zv[0], z1 = zv[1], z2 = zv[2], z3 = zv[3];
                        float4 z4 = zv[4], z5 = zv[5], z6 = zv[6], z7 = zv[7];
                        float v = 0.f;   // ascending-c chain (v6-bitwise values)
                        v = fmaf(w0.x,z0.x,v); v = fmaf(w0.y,z0.y,v);
                        v = fmaf(w0.z,z0.z,v); v = fmaf(w0.w,z0.w,v);
                        v = fmaf(w1.x,z1.x,v); v = fmaf(w1.y,z1.y,v);
                        v = fmaf(w1.z,z1.z,v); v = fmaf(w1.w,z1.w,v);
                        v = fmaf(w2.x,z2.x,v); v = fmaf(w2.y,z2.y,v);
                        v = fmaf(w2.z,z2.z,v); v = fmaf(w2.w,z2.w,v);
                        v = fmaf(w3.x,z3.x,v); v = fmaf(w3.y,z3.y,v);
                        v = fmaf(w3.z,z3.z,v); v = fmaf(w3.w,z3.w,v);
                        v = fmaf(w4.x,z4.x,v); v = fmaf(w4.y,z4.y,v);
                        v = fmaf(w4.z,z4.z,v); v = fmaf(w4.w,z4.w,v);
                        v = fmaf(w5.x,z5.x,v); v = fmaf(w5.y,z5.y,v);
                        v = fmaf(w5.z,z5.z,v); v = fmaf(w5.w,z5.w,v);
                        v = fmaf(w6.x,z6.x,v); v = fmaf(w6.y,z6.y,v);
                        v = fmaf(w6.z,z6.z,v); v = fmaf(w6.w,z6.w,v);
                        v = fmaf(w7.x,z7.x,v); v = fmaf(w7.y,z7.y,v);
                        v = fmaf(w7.z,z7.z,v); v = fmaf(w7.w,z7.w,v);
                        float outv = v + ob;      // bias after contraction
                        R[d*33 + t] = R[d*33 + t] - outv;
                    }
                }
            }
            __syncthreads();
        }

        // quantized_out = x - residual_final
        float* qo = out + (size_t)b * DDIM * TT + t0;
        for (int i = tid; i < DDIM*TILE; i += NTHR) {
            int d = i >> 5, t = i & 31;
            qo[(size_t)d * TT + t] = xg[(size_t)d * TT + t] - R[d*33 + t];
        }
        __syncthreads();
    }

    // ===== Epilogue: deterministic loss reduction (CTAs 0..7) =====
    if (tid == 0) __threadfence();
    grid_barrier(tid);
    if (bid < NQ) {
        float* red = sm;
        int q = bid;
        float s = 0.f;
        for (int i = tid; i < NTILES; i += NTHR) s += g_losspart_v8[q*NTILES + i];
        red[tid] = s;
        __syncthreads();
        for (int o = NTHR/2; o; o >>= 1) {
            if (tid < o) red[tid] += red[tid + o];
            __syncthreads();
        }
        if (tid == 0)
            out[IOFF + q] = 1.25f * red[0] * (1.0f / (float)(BB*CD*TT));
    }
}

// ---------------- launch ----------------
extern "C" void kernel_launch(void* const* d_in, const int* in_sizes, int n_in,
                              void* d_out, int out_size) {
    const float* x     = (const float*)d_in[0];
    const float* in_w  = (const float*)d_in[1];
    const float* in_b  = (const float*)d_in[2];
    const float* out_w = (const float*)d_in[3];
    const float* out_b = (const float*)d_in[4];
    const float* cb    = (const float*)d_in[5];
    float* out = (float*)d_out;

    cudaFuncSetAttribute(rvq_persist_v8, cudaFuncAttributeMaxDynamicSharedMemorySize, SMEM_BYTES);
    rvq_persist_v8<<<NCTA, NTHR, SMEM_BYTES>>>(x, in_w, in_b, out_w, out_b, cb, out);
}

// round 11
// speedup vs baseline: 1.3039x; 1.0306x over previous
#include <cuda_runtime.h>
#include <math.h>

// ---------------- Problem constants ----------------
#define NQ    8
#define DDIM  1024
#define CD    32
#define KC    1024
#define BB    16
#define TT    4096
#define TILE  32
#define NTHR  512
#define NWARP 16
#define NCTA  148
#define NTILES ((BB*TT)/TILE)                // 2048 tiles
#define QOFF  ((size_t)BB*DDIM*TT)
#define IOFF  (QOFF + (size_t)NQ*BB*TT)
#define RTP   1028                            // R_T row pitch (floats)

// Shared memory layout (floats)
#define SM_RT    0                            // R transposed [32][1028] = 32896
#define SM_W     32896                        // two 32x256 buffers = 16384
#define SM_ZE    (SM_W + 2*CD*256)            // 49280  ZE[c*33+t] (1056)
#define SM_ZQ    (SM_ZE + CD*33)              // 50336  ZQ[c*33+t] (1056)
#define SM_ENCT  (SM_ZQ + CD*33)              // 51392  ENC transposed [t][36]
#define SM_ZQST  (SM_ENCT + 32*36)            // 52544  STE z_q transposed [t][36]
#define SM_BV    (SM_ZQST + 32*36)            // 53696
#define SM_BI    (SM_BV + NWARP*32)           // 54208
#define SM_FLOATS (SM_BI + NWARP*32)          // 54720
#define SMEM_BYTES (SM_FLOATS * 4)            // 218880 bytes

__device__ float g_cbn_v9[NQ*KC*CD];
__device__ float g_losspart_v9[NQ*NTILES];
__device__ int   g_tick_v9;

__device__ __forceinline__ void grid_barrier(int tid) {
    __syncthreads();
    if (tid == 0) {
        __threadfence();
        int t = atomicAdd(&g_tick_v9, 1);
        int target = (t / NCTA + 1) * NCTA;
        while (*(volatile int*)&g_tick_v9 < target) { }
        __threadfence();
    }
    __syncthreads();
}

__device__ __forceinline__ unsigned f2ord(float f) {
    int b = __float_as_int(f);
    return (b >= 0) ? ((unsigned)b | 0x80000000u) : ~(unsigned)b;
}

__device__ __forceinline__ void cp_async16(unsigned s, const void* g) {
    asm volatile("cp.async.cg.shared.global [%0], [%1], 16;" :: "r"(s), "l"(g));
}
#define CP_COMMIT() asm volatile("cp.async.commit_group;")
#define CP_WAIT0()  asm volatile("cp.async.wait_group 0;")

// 32-term ascending-c fma chain (bitwise = v8)
#define SIM_CHAIN(sv, A0,A1,A2,A3,A4,A5,A6,A7, E0,E1,E2,E3,E4,E5,E6,E7) \
    sv = 0.f; \
    sv = fmaf(A0.x,E0.x,sv); sv = fmaf(A0.y,E0.y,sv); \
    sv = fmaf(A0.z,E0.z,sv); sv = fmaf(A0.w,E0.w,sv); \
    sv = fmaf(A1.x,E1.x,sv); sv = fmaf(A1.y,E1.y,sv); \
    sv = fmaf(A1.z,E1.z,sv); sv = fmaf(A1.w,E1.w,sv); \
    sv = fmaf(A2.x,E2.x,sv); sv = fmaf(A2.y,E2.y,sv); \
    sv = fmaf(A2.z,E2.z,sv); sv = fmaf(A2.w,E2.w,sv); \
    sv = fmaf(A3.x,E3.x,sv); sv = fmaf(A3.y,E3.y,sv); \
    sv = fmaf(A3.z,E3.z,sv); sv = fmaf(A3.w,E3.w,sv); \
    sv = fmaf(A4.x,E4.x,sv); sv = fmaf(A4.y,E4.y,sv); \
    sv = fmaf(A4.z,E4.z,sv); sv = fmaf(A4.w,E4.w,sv); \
    sv = fmaf(A5.x,E5.x,sv); sv = fmaf(A5.y,E5.y,sv); \
    sv = fmaf(A5.z,E5.z,sv); sv = fmaf(A5.w,E5.w,sv); \
    sv = fmaf(A6.x,E6.x,sv); sv = fmaf(A6.y,E6.y,sv); \
    sv = fmaf(A6.z,E6.z,sv); sv = fmaf(A6.w,E6.w,sv); \
    sv = fmaf(A7.x,E7.x,sv); sv = fmaf(A7.y,E7.y,sv); \
    sv = fmaf(A7.z,E7.z,sv); sv = fmaf(A7.w,E7.w,sv);

// ---------------- Single persistent kernel ----------------
__global__ __launch_bounds__(NTHR, 1)
void rvq_persist_v9(const float* __restrict__ x,
                    const float* __restrict__ in_w,
                    const float* __restrict__ in_b,
                    const float* __restrict__ out_w,
                    const float* __restrict__ out_b,
                    const float* __restrict__ cb,
                    float* __restrict__ out)
{
    extern __shared__ float sm[];
    float* RT   = sm + SM_RT;
    float* W0   = sm + SM_W;
    float* W1   = sm + SM_W + CD*256;
    float* ZE   = sm + SM_ZE;
    float* ZQ   = sm + SM_ZQ;
    float* ENCT = sm + SM_ENCT;
    float* ZQST = sm + SM_ZQST;
    float* BV   = sm + SM_BV;
    int*   BI   = (int*)(sm + SM_BI);

    const int tid  = threadIdx.x;
    const int lane = tid & 31;
    const int wg   = tid >> 5;               // 0..15
    const int bid  = blockIdx.x;

    // ===== Prologue: normalize codebook rows (jnp rounding mimicry) =====
    {
        int gid = bid * NTHR + tid;
        if (gid < NQ*KC) {
            const float* src = cb + (size_t)gid * CD;
            float v[CD];
            float ss = 0.f;
#pragma unroll
            for (int c = 0; c < CD; c++) {
                v[c] = src[c];
                float vv = v[c] * v[c];
                ss = ss + vv;
            }
            float n = fmaxf(sqrtf(ss), 1e-12f);
            float* dst = g_cbn_v9 + (size_t)gid * CD;
#pragma unroll
            for (int c = 0; c < CD; c++) dst[c] = v[c] / n;
            __threadfence();
        }
    }
    grid_barrier(tid);

    // ===== Tile loop =====
    for (int blk = bid; blk < NTILES; blk += NCTA) {
        const int b  = blk >> 7;
        const int t0 = (blk & 127) << 5;
        const float* xg = x + (size_t)b * DDIM * TT + t0;

        // load residual tile transposed: RT[t][d]
        for (int i = tid; i < DDIM*TILE; i += NTHR) {
            int d = i >> 5, t = i & 31;
            RT[t*RTP + d] = xg[(size_t)d * TT + t];
        }
        __syncthreads();

        for (int q = 0; q < NQ; q++) {
            const float* inw_q = in_w + (size_t)q * CD * DDIM;

            // pre-stage W chunk 0 via cp.async (all threads)
            {
                unsigned wb = (unsigned)__cvta_generic_to_shared(W0);
                for (int j = tid; j < CD*64; j += NTHR) {
                    int c = j >> 6, dq = j & 63;
                    cp_async16(wb + j*16, inw_q + (size_t)c*DDIM + dq*4);
                }
                CP_COMMIT();
            }

            // ===== Phase A: z_e = in_w @ R (16 warps x 2 ch; v6-bitwise chains) =====
            const int c0 = wg * 2;
            float acc0 = 0.f, acc1 = 0.f;

            for (int ci = 0; ci < 4; ci++) {
                CP_WAIT0();
                __syncthreads();     // chunk ci visible; buffer (ci+1)&1 free
                if (ci < 3) {        // stage next chunk, overlapped with compute
                    float* Wn = ((ci+1) & 1) ? W1 : W0;
                    unsigned wb = (unsigned)__cvta_generic_to_shared(Wn);
                    const int dcn = (ci+1) * 256;
                    for (int j = tid; j < CD*64; j += NTHR) {
                        int c = j >> 6, dq = j & 63;
                        cp_async16(wb + j*16, inw_q + (size_t)c*DDIM + dcn + dq*4);
                    }
                    CP_COMMIT();
                }
                const int dc = ci * 256;
                const float* Wb  = (ci & 1) ? W1 : W0;
                const float* Wr0 = Wb + (c0+0)*256;
                const float* Wr1 = Wb + (c0+1)*256;
                const float* Rrow = RT + lane*RTP + dc;
#pragma unroll 8
                for (int dd = 0; dd < 256; dd += 4) {
                    float4 rv = *(const float4*)(Rrow + dd);
                    float4 w0 = *(const float4*)(Wr0 + dd);
                    float4 w1 = *(const float4*)(Wr1 + dd);
                    // strict ascending d within group (bitwise = v6/v8)
                    acc0 = fmaf(w0.x, rv.x, acc0); acc0 = fmaf(w0.y, rv.y, acc0);
                    acc0 = fmaf(w0.z, rv.z, acc0); acc0 = fmaf(w0.w, rv.w, acc0);
                    acc1 = fmaf(w1.x, rv.x, acc1); acc1 = fmaf(w1.y, rv.y, acc1);
                    acc1 = fmaf(w1.z, rv.z, acc1); acc1 = fmaf(w1.w, rv.w, acc1);
                }
                if (ci < 3) __syncthreads();  // protect buffer reuse next iter
            }
            {
                const float* inb_q = in_b + q*CD;    // bias AFTER contraction
                ZE[(c0+0)*33 + lane] = acc0 + __ldg(inb_q + c0 + 0);
                ZE[(c0+1)*33 + lane] = acc1 + __ldg(inb_q + c0 + 1);
            }
            __syncthreads();

            // prefetch both cbn rows (hidden behind warp0's enc)
            const float* cbn_q = g_cbn_v9 + (size_t)q * KC * CD;
            const float4* rp0 = (const float4*)(cbn_q + (size_t)(wg*64 + lane) * CD);
            const float4* rp1 = (const float4*)(cbn_q + (size_t)(wg*64 + 32 + lane) * CD);
            float4 ra0 = __ldg(rp0+0), ra1 = __ldg(rp0+1), ra2 = __ldg(rp0+2), ra3 = __ldg(rp0+3);
            float4 ra4 = __ldg(rp0+4), ra5 = __ldg(rp0+5), ra6 = __ldg(rp0+6), ra7 = __ldg(rp0+7);
            float4 rb0 = __ldg(rp1+0), rb1 = __ldg(rp1+1), rb2 = __ldg(rp1+2), rb3 = __ldg(rp1+3);
            float4 rb4 = __ldg(rp1+4), rb5 = __ldg(rp1+5), rb6 = __ldg(rp1+6), rb7 = __ldg(rp1+7);

            // ===== enc (v6-bitwise values), transposed store =====
            if (wg == 0) {
                float n2 = 0.f;
#pragma unroll
                for (int c = 0; c < CD; c++) {
                    float z = ZE[c*33 + lane];
                    float zz = z * z;
                    n2 = n2 + zz;
                }
                float n = fmaxf(sqrtf(n2), 1e-12f);
#pragma unroll
                for (int c = 0; c < CD; c++)
                    ENCT[lane*36 + c] = ZE[c*33 + lane] / n;
            }
            __syncthreads();

            // ===== Phase B: cached rows, single t-loop (semantics = v8) =====
            {
                float bestv = 0.f; int bestk = 0;
                for (int t = 0; t < TILE; t++) {
                    const float4* ev = (const float4*)(ENCT + t*36);
                    float4 e0 = ev[0], e1 = ev[1], e2 = ev[2], e3 = ev[3];
                    float4 e4 = ev[4], e5 = ev[5], e6 = ev[6], e7 = ev[7];
                    float s0, s1;
                    SIM_CHAIN(s0, ra0,ra1,ra2,ra3,ra4,ra5,ra6,ra7, e0,e1,e2,e3,e4,e5,e6,e7);
                    SIM_CHAIN(s1, rb0,rb1,rb2,rb3,rb4,rb5,rb6,rb7, e0,e1,e2,e3,e4,e5,e6,e7);
                    // batch 0 argmax (first occurrence)
                    unsigned u0 = f2ord(s0);
                    unsigned m0 = __reduce_max_sync(0xffffffffu, u0);
                    unsigned q0 = __ballot_sync(0xffffffffu, u0 == m0);
                    int l0 = __ffs(q0) - 1;
                    float sb0 = __shfl_sync(0xffffffffu, s0, l0);
                    int   kb0 = wg*64 + l0;
                    // batch 1
                    unsigned u1 = f2ord(s1);
                    unsigned m1 = __reduce_max_sync(0xffffffffu, u1);
                    unsigned q1 = __ballot_sync(0xffffffffu, u1 == m1);
                    int l1 = __ffs(q1) - 1;
                    float sb1 = __shfl_sync(0xffffffffu, s1, l1);
                    int   kb1 = wg*64 + 32 + l1;
                    // merge: strict > keeps lower k (= v8 batch order)
                    float bv = sb0; int bk = kb0;
                    if (sb1 > bv) { bv = sb1; bk = kb1; }
                    if (lane == t) { bestv = bv; bestk = bk; }
                }
                BV[wg*32 + lane] = bestv;
                BI[wg*32 + lane] = bestk;
            }
            __syncthreads();

            // cross-warp merge (ascending code ranges; strict >)
            if (wg == 0) {
                float fb = BV[lane]; int fi = BI[lane];
#pragma unroll
                for (int w2 = 1; w2 < NWARP; w2++) {
                    float v = BV[w2*32 + lane];
                    if (v > fb) { fb = v; fi = BI[w2*32 + lane]; }
                }
                BI[lane] = fi;
                out[QOFF + ((size_t)q * BB + b) * TT + t0 + lane] = (float)fi;
            }
            __syncthreads();

            // gather z_q = cb[q][idx]
            {
                const float* cb_q = cb + (size_t)q * KC * CD;
                for (int i = tid; i < CD*TILE; i += NTHR) {
                    int c = i >> 5, t = i & 31;
                    ZQ[c*33 + t] = __ldg(cb_q + (size_t)BI[t] * CD + c);
                }
            }
            __syncthreads();

            // prefetch out_w rows for Phase C (hidden behind loss section)
            const float* outw_q = out_w + (size_t)q * DDIM * CD;
            const float* outb_q = out_b + (size_t)q * DDIM;
            const int d0 = wg*64 + lane, d1 = d0 + 32;
            const float4* wp0 = (const float4*)(outw_q + (size_t)d0 * CD);
            const float4* wp1 = (const float4*)(outw_q + (size_t)d1 * CD);
            float4 wa0 = __ldg(wp0+0), wa1 = __ldg(wp0+1), wa2 = __ldg(wp0+2), wa3 = __ldg(wp0+3);
            float4 wa4 = __ldg(wp0+4), wa5 = __ldg(wp0+5), wa6 = __ldg(wp0+6), wa7 = __ldg(wp0+7);
            float4 wb0 = __ldg(wp1+0), wb1 = __ldg(wp1+1), wb2 = __ldg(wp1+2), wb3 = __ldg(wp1+3);
            float4 wb4 = __ldg(wp1+4), wb5 = __ldg(wp1+5), wb6 = __ldg(wp1+6), wb7 = __ldg(wp1+7);
            float ob0 = __ldg(outb_q + d0), ob1 = __ldg(outb_q + d1);

            // loss partial (raw z_q; v8-bitwise chain) + STE transposed build
            {
                float lp = 0.f;
                for (int i = tid; i < CD*TILE; i += NTHR) {
                    int c = i >> 5, t = i & 31;
                    float ze = ZE[c*33 + t];
                    float zq = ZQ[c*33 + t];
                    float dv = ze - zq;
                    lp = fmaf(dv, dv, lp);
                    float dlt = zq - ze;          // STE: fl(z_e + fl(z_q - z_e))
                    ZQST[t*36 + c] = ze + dlt;
                }
#pragma unroll
                for (int o = 16; o; o >>= 1) lp += __shfl_down_sync(0xffffffffu, lp, o);
                if (lane == 0) BV[wg] = lp;
            }
            __syncthreads();
            if (tid == 0) {
                float s = 0.f;
#pragma unroll
                for (int w2 = 0; w2 < NWARP; w2++) s += BV[w2];
                g_losspart_v9[q*NTILES + blk] = s;
            }

            // ===== Phase C: cached rows, single t-loop (values = v8) =====
            {
                for (int t = 0; t < TILE; t++) {
                    const float4* zv = (const float4*)(ZQST + t*36);
                    float4 z0 = zv[0], z1 = zv[1], z2 = zv[2], z3 = zv[3];
                    float4 z4 = zv[4], z5 = zv[5], z6 = zv[6], z7 = zv[7];
                    float v0, v1;
                    SIM_CHAIN(v0, wa0,wa1,wa2,wa3,wa4,wa5,wa6,wa7, z0,z1,z2,z3,z4,z5,z6,z7);
                    SIM_CHAIN(v1, wb0,wb1,wb2,wb3,wb4,wb5,wb6,wb7, z0,z1,z2,z3,z4,z5,z6,z7);
                    float o0 = v0 + ob0;          // bias after contraction
                    float o1 = v1 + ob1;
                    RT[t*RTP + d0] = RT[t*RTP + d0] - o0;
                    RT[t*RTP + d1] = RT[t*RTP + d1] - o1;
                }
            }
            __syncthreads();
        }

        // quantized_out = x - residual_final
        float* qo = out + (size_t)b * DDIM * TT + t0;
        for (int i = tid; i < DDIM*TILE; i += NTHR) {
            int d = i >> 5, t = i & 31;
            qo[(size_t)d * TT + t] = xg[(size_t)d * TT + t] - RT[t*RTP + d];
        }
        __syncthreads();
    }

    // ===== Epilogue: deterministic loss reduction (CTAs 0..7) =====
    if (tid == 0) __threadfence();
    grid_barrier(tid);
    if (bid < NQ) {
        float* red = sm;
        int q = bid;
        float s = 0.f;
        for (int i = tid; i < NTILES; i += NTHR) s += g_losspart_v9[q*NTILES + i];
        red[tid] = s;
        __syncthreads();
        for (int o = NTHR/2; o; o >>= 1) {
            if (tid < o) red[tid] += red[tid + o];
            __syncthreads();
        }
        if (tid == 0)
            out[IOFF + q] = 1.25f * red[0] * (1.0f / (float)(BB*CD*TT));
    }
}

// ---------------- launch ----------------
extern "C" void kernel_launch(void* const* d_in, const int* in_sizes, int n_in,
                              void* d_out, int out_size) {
    const float* x     = (const float*)d_in[0];
    const float* in_w  = (const float*)d_in[1];
    const float* in_b  = (const float*)d_in[2];
    const float* out_w = (const float*)d_in[3];
    const float* out_b = (const float*)d_in[4];
    const float* cb    = (const float*)d_in[5];
    float* out = (float*)d_out;

    cudaFuncSetAttribute(rvq_persist_v9, cudaFuncAttributeMaxDynamicSharedMemorySize, SMEM_BYTES);
    rvq_persist_v9<<<NCTA, NTHR, SMEM_BYTES>>>(x, in_w, in_b, out_w, out_b, cb, out);
}

// round 14
// speedup vs baseline: 1.4082x; 1.0800x over previous
#include <cuda_runtime.h>
#include <math.h>

// ---------------- Problem constants ----------------
#define NQ    8
#define DDIM  1024
#define CD    32
#define KC    1024
#define BB    16
#define TT    4096
#define TILE  32
#define NTHR  512
#define NWARP 16
#define NCTA  148
#define NTILES ((BB*TT)/TILE)                // 2048 tiles
#define QOFF  ((size_t)BB*DDIM*TT)
#define IOFF  (QOFF + (size_t)NQ*BB*TT)
#define RTP   1028                            // R_T row pitch (floats)

// Shared memory layout (floats)
#define SM_RT    0                            // R transposed [32][1028] = 32896
#define SM_W     32896                        // two 32x256 buffers = 16384
#define SM_ZE    (SM_W + 2*CD*256)            // 49280  ZE[c*33+t]
#define SM_ENCT  (SM_ZE + CD*33)              // 50336  ENC transposed [t][36]
#define SM_ZQST  (SM_ENCT + 32*36)            // 51488  STE z_q transposed [t][36]
#define SM_BV    (SM_ZQST + 32*36)            // 52640
#define SM_BI    (SM_BV + NWARP*32)           // 53152
#define SM_FLOATS (SM_BI + NWARP*32)          // 53664
#define SMEM_BYTES (SM_FLOATS * 4)            // 214656 bytes

__device__ float g_cbn_v10[NQ*KC*CD];
__device__ float g_losspart_v10[NQ*NTILES];
__device__ int   g_tick_v10;

__device__ __forceinline__ void grid_barrier(int tid) {
    __syncthreads();
    if (tid == 0) {
        __threadfence();
        int t = atomicAdd(&g_tick_v10, 1);
        int target = (t / NCTA + 1) * NCTA;
        while (*(volatile int*)&g_tick_v10 < target) { }
        __threadfence();
    }
    __syncthreads();
}

__device__ __forceinline__ unsigned f2ord(float f) {
    int b = __float_as_int(f);
    return (b >= 0) ? ((unsigned)b | 0x80000000u) : ~(unsigned)b;
}

__device__ __forceinline__ void cp_async16(unsigned s, const void* g) {
    asm volatile("cp.async.cg.shared.global [%0], [%1], 16;" :: "r"(s), "l"(g));
}
#define CP_COMMIT() asm volatile("cp.async.commit_group;")
#define CP_WAIT0()  asm volatile("cp.async.wait_group 0;")

// 32-term ascending-c fma chain (bitwise = v8/v9)
#define SIM_CHAIN(sv, A0,A1,A2,A3,A4,A5,A6,A7, E0,E1,E2,E3,E4,E5,E6,E7) \
    sv = 0.f; \
    sv = fmaf(A0.x,E0.x,sv); sv = fmaf(A0.y,E0.y,sv); \
    sv = fmaf(A0.z,E0.z,sv); sv = fmaf(A0.w,E0.w,sv); \
    sv = fmaf(A1.x,E1.x,sv); sv = fmaf(A1.y,E1.y,sv); \
    sv = fmaf(A1.z,E1.z,sv); sv = fmaf(A1.w,E1.w,sv); \
    sv = fmaf(A2.x,E2.x,sv); sv = fmaf(A2.y,E2.y,sv); \
    sv = fmaf(A2.z,E2.z,sv); sv = fmaf(A2.w,E2.w,sv); \
    sv = fmaf(A3.x,E3.x,sv); sv = fmaf(A3.y,E3.y,sv); \
    sv = fmaf(A3.z,E3.z,sv); sv = fmaf(A3.w,E3.w,sv); \
    sv = fmaf(A4.x,E4.x,sv); sv = fmaf(A4.y,E4.y,sv); \
    sv = fmaf(A4.z,E4.z,sv); sv = fmaf(A4.w,E4.w,sv); \
    sv = fmaf(A5.x,E5.x,sv); sv = fmaf(A5.y,E5.y,sv); \
    sv = fmaf(A5.z,E5.z,sv); sv = fmaf(A5.w,E5.w,sv); \
    sv = fmaf(A6.x,E6.x,sv); sv = fmaf(A6.y,E6.y,sv); \
    sv = fmaf(A6.z,E6.z,sv); sv = fmaf(A6.w,E6.w,sv); \
    sv = fmaf(A7.x,E7.x,sv); sv = fmaf(A7.y,E7.y,sv); \
    sv = fmaf(A7.z,E7.z,sv); sv = fmaf(A7.w,E7.w,sv);

// ---------------- Single persistent kernel ----------------
__global__ __launch_bounds__(NTHR, 1)
void rvq_persist_v10(const float* __restrict__ x,
                     const float* __restrict__ in_w,
                     const float* __restrict__ in_b,
                     const float* __restrict__ out_w,
                     const float* __restrict__ out_b,
                     const float* __restrict__ cb,
                     float* __restrict__ out)
{
    extern __shared__ float sm[];
    float* RT   = sm + SM_RT;
    float* W0   = sm + SM_W;
    float* W1   = sm + SM_W + CD*256;
    float* ZE   = sm + SM_ZE;
    float* ENCT = sm + SM_ENCT;
    float* ZQST = sm + SM_ZQST;
    float* BV   = sm + SM_BV;
    int*   BI   = (int*)(sm + SM_BI);

    const int tid  = threadIdx.x;
    const int lane = tid & 31;
    const int wg   = tid >> 5;               // 0..15
    const int bid  = blockIdx.x;

    // ===== Prologue: normalize codebook rows (jnp rounding mimicry) =====
    {
        int gid = bid * NTHR + tid;
        if (gid < NQ*KC) {
            const float* src = cb + (size_t)gid * CD;
            float v[CD];
            float ss = 0.f;
#pragma unroll
            for (int c = 0; c < CD; c++) {
                v[c] = src[c];
                float vv = v[c] * v[c];
                ss = ss + vv;
            }
            float n = fmaxf(sqrtf(ss), 1e-12f);
            float* dst = g_cbn_v10 + (size_t)gid * CD;
#pragma unroll
            for (int c = 0; c < CD; c++) dst[c] = v[c] / n;
            __threadfence();
        }
    }
    grid_barrier(tid);

    // ===== Tile loop =====
    for (int blk = bid; blk < NTILES; blk += NCTA) {
        const int b  = blk >> 7;
        const int t0 = (blk & 127) << 5;
        const float* xg = x + (size_t)b * DDIM * TT + t0;

        // load residual tile transposed: RT[t][d]
        for (int i = tid; i < DDIM*TILE; i += NTHR) {
            int d = i >> 5, t = i & 31;
            RT[t*RTP + d] = xg[(size_t)d * TT + t];
        }
        __syncthreads();

        for (int q = 0; q < NQ; q++) {
            const float* inw_q = in_w + (size_t)q * CD * DDIM;

            // pre-stage W chunk 0 via cp.async (all threads)
            {
                unsigned wb = (unsigned)__cvta_generic_to_shared(W0);
                for (int j = tid; j < CD*64; j += NTHR) {
                    int c = j >> 6, dq = j & 63;
                    cp_async16(wb + j*16, inw_q + (size_t)c*DDIM + dq*4);
                }
                CP_COMMIT();
            }

            // ===== Phase A: z_e = in_w @ R (8 warps x 4 ch; v5/v7-bitwise) =====
            const int c0 = (wg & 7) * 4;
            float acc0 = 0.f, acc1 = 0.f, acc2 = 0.f, acc3 = 0.f;

            for (int ci = 0; ci < 4; ci++) {
                CP_WAIT0();
                __syncthreads();     // chunk ci visible
                if (ci < 3) {        // stage next chunk (all threads), overlapped
                    float* Wn = ((ci+1) & 1) ? W1 : W0;
                    unsigned wb = (unsigned)__cvta_generic_to_shared(Wn);
                    const int dcn = (ci+1) * 256;
                    for (int j = tid; j < CD*64; j += NTHR) {
                        int c = j >> 6, dq = j & 63;
                        cp_async16(wb + j*16, inw_q + (size_t)c*DDIM + dcn + dq*4);
                    }
                    CP_COMMIT();
                }
                if (wg < 8) {
                    const int dc = ci * 256;
                    const float* Wb  = (ci & 1) ? W1 : W0;
                    const float* Wr0 = Wb + (c0+0)*256;
                    const float* Wr1 = Wb + (c0+1)*256;
                    const float* Wr2 = Wb + (c0+2)*256;
                    const float* Wr3 = Wb + (c0+3)*256;
                    const float* Rrow = RT + lane*RTP + dc;
#pragma unroll 4
                    for (int dd = 0; dd < 256; dd += 4) {
                        float4 rv = *(const float4*)(Rrow + dd);
                        float4 w0 = *(const float4*)(Wr0 + dd);
                        float4 w1 = *(const float4*)(Wr1 + dd);
                        float4 w2 = *(const float4*)(Wr2 + dd);
                        float4 w3 = *(const float4*)(Wr3 + dd);
                        // strict ascending d within group (bitwise = v5/v7)
                        acc0 = fmaf(w0.x, rv.x, acc0); acc0 = fmaf(w0.y, rv.y, acc0);
                        acc0 = fmaf(w0.z, rv.z, acc0); acc0 = fmaf(w0.w, rv.w, acc0);
                        acc1 = fmaf(w1.x, rv.x, acc1); acc1 = fmaf(w1.y, rv.y, acc1);
                        acc1 = fmaf(w1.z, rv.z, acc1); acc1 = fmaf(w1.w, rv.w, acc1);
                        acc2 = fmaf(w2.x, rv.x, acc2); acc2 = fmaf(w2.y, rv.y, acc2);
                        acc2 = fmaf(w2.z, rv.z, acc2); acc2 = fmaf(w2.w, rv.w, acc2);
                        acc3 = fmaf(w3.x, rv.x, acc3); acc3 = fmaf(w3.y, rv.y, acc3);
                        acc3 = fmaf(w3.z, rv.z, acc3); acc3 = fmaf(w3.w, rv.w, acc3);
                    }
                }
                if (ci < 3) __syncthreads();  // protect buffer reuse
            }
            if (wg < 8) {
                const float* inb_q = in_b + q*CD;    // bias AFTER contraction
                ZE[(c0+0)*33 + lane] = acc0 + __ldg(inb_q + c0 + 0);
                ZE[(c0+1)*33 + lane] = acc1 + __ldg(inb_q + c0 + 1);
                ZE[(c0+2)*33 + lane] = acc2 + __ldg(inb_q + c0 + 2);
                ZE[(c0+3)*33 + lane] = acc3 + __ldg(inb_q + c0 + 3);
            }
            __syncthreads();

            // prefetch both cbn rows (hidden behind warp0's enc)
            const float* cbn_q = g_cbn_v10 + (size_t)q * KC * CD;
            const float4* rp0 = (const float4*)(cbn_q + (size_t)(wg*64 + lane) * CD);
            const float4* rp1 = (const float4*)(cbn_q + (size_t)(wg*64 + 32 + lane) * CD);
            float4 ra0 = __ldg(rp0+0), ra1 = __ldg(rp0+1), ra2 = __ldg(rp0+2), ra3 = __ldg(rp0+3);
            float4 ra4 = __ldg(rp0+4), ra5 = __ldg(rp0+5), ra6 = __ldg(rp0+6), ra7 = __ldg(rp0+7);
            float4 rb0 = __ldg(rp1+0), rb1 = __ldg(rp1+1), rb2 = __ldg(rp1+2), rb3 = __ldg(rp1+3);
            float4 rb4 = __ldg(rp1+4), rb5 = __ldg(rp1+5), rb6 = __ldg(rp1+6), rb7 = __ldg(rp1+7);

            // ===== enc (bitwise = v6/v9), transposed store =====
            if (wg == 0) {
                float n2 = 0.f;
#pragma unroll
                for (int c = 0; c < CD; c++) {
                    float z = ZE[c*33 + lane];
                    float zz = z * z;
                    n2 = n2 + zz;
                }
                float n = fmaxf(sqrtf(n2), 1e-12f);
#pragma unroll
                for (int c = 0; c < CD; c++)
                    ENCT[lane*36 + c] = ZE[c*33 + lane] / n;
            }
            __syncthreads();

            // ===== Phase B: cached rows, single t-loop (semantics = v8/v9) =====
            {
                float bestv = 0.f; int bestk = 0;
                for (int t = 0; t < TILE; t++) {
                    const float4* ev = (const float4*)(ENCT + t*36);
                    float4 e0 = ev[0], e1 = ev[1], e2 = ev[2], e3 = ev[3];
                    float4 e4 = ev[4], e5 = ev[5], e6 = ev[6], e7 = ev[7];
                    float s0, s1;
                    SIM_CHAIN(s0, ra0,ra1,ra2,ra3,ra4,ra5,ra6,ra7, e0,e1,e2,e3,e4,e5,e6,e7);
                    SIM_CHAIN(s1, rb0,rb1,rb2,rb3,rb4,rb5,rb6,rb7, e0,e1,e2,e3,e4,e5,e6,e7);
                    unsigned u0 = f2ord(s0);
                    unsigned m0 = __reduce_max_sync(0xffffffffu, u0);
                    unsigned q0 = __ballot_sync(0xffffffffu, u0 == m0);
                    int l0 = __ffs(q0) - 1;
                    float sb0 = __shfl_sync(0xffffffffu, s0, l0);
                    int   kb0 = wg*64 + l0;
                    unsigned u1 = f2ord(s1);
                    unsigned m1 = __reduce_max_sync(0xffffffffu, u1);
                    unsigned q1 = __ballot_sync(0xffffffffu, u1 == m1);
                    int l1 = __ffs(q1) - 1;
                    float sb1 = __shfl_sync(0xffffffffu, s1, l1);
                    int   kb1 = wg*64 + 32 + l1;
                    float bv = sb0; int bk = kb0;
                    if (sb1 > bv) { bv = sb1; bk = kb1; }
                    if (lane == t) { bestv = bv; bestk = bk; }
                }
                BV[wg*32 + lane] = bestv;
                BI[wg*32 + lane] = bestk;
            }
            __syncthreads();

            // cross-warp merge (ascending code ranges; strict >)
            if (wg == 0) {
                float fb = BV[lane]; int fi = BI[lane];
#pragma unroll
                for (int w2 = 1; w2 < NWARP; w2++) {
                    float v = BV[w2*32 + lane];
                    if (v > fb) { fb = v; fi = BI[w2*32 + lane]; }
                }
                BI[lane] = fi;
                out[QOFF + ((size_t)q * BB + b) * TT + t0 + lane] = (float)fi;
            }
            __syncthreads();

            // prefetch out_w rows for Phase C (hidden behind loss section)
            const float* outw_q = out_w + (size_t)q * DDIM * CD;
            const float* outb_q = out_b + (size_t)q * DDIM;
            const int d0 = wg*64 + lane, d1 = d0 + 32;
            const float4* wp0 = (const float4*)(outw_q + (size_t)d0 * CD);
            const float4* wp1 = (const float4*)(outw_q + (size_t)d1 * CD);
            float4 wa0 = __ldg(wp0+0), wa1 = __ldg(wp0+1), wa2 = __ldg(wp0+2), wa3 = __ldg(wp0+3);
            float4 wa4 = __ldg(wp0+4), wa5 = __ldg(wp0+5), wa6 = __ldg(wp0+6), wa7 = __ldg(wp0+7);
            float4 wb0 = __ldg(wp1+0), wb1 = __ldg(wp1+1), wb2 = __ldg(wp1+2), wb3 = __ldg(wp1+3);
            float4 wb4 = __ldg(wp1+4), wb5 = __ldg(wp1+5), wb6 = __ldg(wp1+6), wb7 = __ldg(wp1+7);
            float ob0 = __ldg(outb_q + d0), ob1 = __ldg(outb_q + d1);

            // loss partial + STE build, z_q gathered DIRECTLY from gmem
            {
                const float* cb_q = cb + (size_t)q * KC * CD;
                float lp = 0.f;
                for (int i = tid; i < CD*TILE; i += NTHR) {
                    int c = i >> 5, t = i & 31;
                    float ze = ZE[c*33 + t];
                    float zq = __ldg(cb_q + (size_t)BI[t] * CD + c);
                    float dv = ze - zq;
                    lp = fmaf(dv, dv, lp);
                    float dlt = zq - ze;          // STE: fl(z_e + fl(z_q - z_e))
                    ZQST[t*36 + c] = ze + dlt;
                }
#pragma unroll
                for (int o = 16; o; o >>= 1) lp += __shfl_down_sync(0xffffffffu, lp, o);
                if (lane == 0) BV[wg] = lp;
            }
            __syncthreads();
            if (tid == 0) {
                float s = 0.f;
#pragma unroll
                for (int w2 = 0; w2 < NWARP; w2++) s += BV[w2];
                g_losspart_v10[q*NTILES + blk] = s;
            }

            // ===== Phase C: cached rows, single t-loop (values = v8/v9) =====
            {
                for (int t = 0; t < TILE; t++) {
                    const float4* zv = (const float4*)(ZQST + t*36);
                    float4 z0 = zv[0], z1 = zv[1], z2 = zv[2], z3 = zv[3];
                    float4 z4 = zv[4], z5 = zv[5], z6 = zv[6], z7 = zv[7];
                    float v0, v1;
                    SIM_CHAIN(v0, wa0,wa1,wa2,wa3,wa4,wa5,wa6,wa7, z0,z1,z2,z3,z4,z5,z6,z7);
                    SIM_CHAIN(v1, wb0,wb1,wb2,wb3,wb4,wb5,wb6,wb7, z0,z1,z2,z3,z4,z5,z6,z7);
                    float o0 = v0 + ob0;          // bias after contraction
                    float o1 = v1 + ob1;
                    RT[t*RTP + d0] = RT[t*RTP + d0] - o0;
                    RT[t*RTP + d1] = RT[t*RTP + d1] - o1;
                }
            }
            __syncthreads();
        }

        // quantized_out = x - residual_final
        float* qo = out + (size_t)b * DDIM * TT + t0;
        for (int i = tid; i < DDIM*TILE; i += NTHR) {
            int d = i >> 5, t = i & 31;
            qo[(size_t)d * TT + t] = xg[(size_t)d * TT + t] - RT[t*RTP + d];
        }
        __syncthreads();
    }

    // ===== Epilogue: deterministic loss reduction (CTAs 0..7) =====
    if (tid == 0) __threadfence();
    grid_barrier(tid);
    if (bid < NQ) {
        float* red = sm;
        int q = bid;
        float s = 0.f;
        for (int i = tid; i < NTILES; i += NTHR) s += g_losspart_v10[q*NTILES + i];
        red[tid] = s;
        __syncthreads();
        for (int o = NTHR/2; o; o >>= 1) {
            if (tid < o) red[tid] += red[tid + o];
            __syncthreads();
        }
        if (tid == 0)
            out[IOFF + q] = 1.25f * red[0] * (1.0f / (float)(BB*CD*TT));
    }
}

// ---------------- launch ----------------
extern "C" void kernel_launch(void* const* d_in, const int* in_sizes, int n_in,
                              void* d_out, int out_size) {
    const float* x     = (const float*)d_in[0];
    const float* in_w  = (const float*)d_in[1];
    const float* in_b  = (const float*)d_in[2];
    const float* out_w = (const float*)d_in[3];
    const float* out_b = (const float*)d_in[4];
    const float* cb    = (const float*)d_in[5];
    float* out = (float*)d_out;

    cudaFuncSetAttribute(rvq_persist_v10, cudaFuncAttributeMaxDynamicSharedMemorySize, SMEM_BYTES);
    rvq_persist_v10<<<NCTA, NTHR, SMEM_BYTES>>>(x, in_w, in_b, out_w, out_b, cb, out);
}